// round 2
// baseline (speedup 1.0000x reference)
#include <cuda_runtime.h>
#include <math.h>

#define B_  2
#define S_  2048
#define D_  1024
#define H_  16
#define HD_ 64
#define KSEL 409
#define RANK0 (S_ - KSEL)   /* 1639: 0-indexed ascending rank of k-th largest */

// ---------------- device scratch (no allocations allowed) ----------------
__device__ float g_Q[B_ * S_ * D_];   // [b,h,s,hd]
__device__ float g_K[B_ * S_ * D_];   // [b,h,s,hd]
__device__ float g_V[B_ * S_ * D_];   // [b,h,s,hd]
__device__ float g_A[B_ * S_ * D_];   // [b,s,d] attention output

// ---------------- SGEMM: C = A(MxK) @ W(NxK)^T + bias ----------------
#define BM 128
#define BN 128
#define BKK 8

__global__ __launch_bounds__(256) void sgemm_bt(
    const float* __restrict__ A, const float* __restrict__ W,
    const float* __restrict__ bias, float* __restrict__ C,
    int M, int N, int K, int headLayout)
{
    __shared__ float As[BKK][BM];
    __shared__ float Bs[BKK][BN];

    int tid = threadIdx.x;
    int bm = blockIdx.y * BM;
    int bn = blockIdx.x * BN;

    int arow = tid >> 1;          // 0..127
    int acol = (tid & 1) * 4;     // 0 or 4
    int tx = tid & 15;            // 0..15
    int ty = tid >> 4;            // 0..15

    float acc[8][8];
#pragma unroll
    for (int i = 0; i < 8; i++)
#pragma unroll
        for (int j = 0; j < 8; j++) acc[i][j] = 0.f;

    for (int k0 = 0; k0 < K; k0 += BKK) {
        float4 a4 = *(const float4*)(A + (size_t)(bm + arow) * K + k0 + acol);
        As[acol + 0][arow] = a4.x; As[acol + 1][arow] = a4.y;
        As[acol + 2][arow] = a4.z; As[acol + 3][arow] = a4.w;
        float4 b4 = *(const float4*)(W + (size_t)(bn + arow) * K + k0 + acol);
        Bs[acol + 0][arow] = b4.x; Bs[acol + 1][arow] = b4.y;
        Bs[acol + 2][arow] = b4.z; Bs[acol + 3][arow] = b4.w;
        __syncthreads();

#pragma unroll
        for (int kk = 0; kk < BKK; kk++) {
            float ar[8], br[8];
            *(float4*)&ar[0] = *(const float4*)&As[kk][ty * 4];
            *(float4*)&ar[4] = *(const float4*)&As[kk][64 + ty * 4];
            *(float4*)&br[0] = *(const float4*)&Bs[kk][tx * 4];
            *(float4*)&br[4] = *(const float4*)&Bs[kk][64 + tx * 4];
#pragma unroll
            for (int i = 0; i < 8; i++)
#pragma unroll
                for (int j = 0; j < 8; j++)
                    acc[i][j] += ar[i] * br[j];
        }
        __syncthreads();
    }

#pragma unroll
    for (int i = 0; i < 8; i++) {
        int r = bm + ((i < 4) ? (ty * 4 + i) : (64 + ty * 4 + i - 4));
#pragma unroll
        for (int j = 0; j < 8; j++) {
            int c = bn + ((j < 4) ? (tx * 4 + j) : (64 + tx * 4 + j - 4));
            float v = acc[i][j] + bias[c];
            if (headLayout) {
                int b = r >> 11;         // r / S_
                int s = r & (S_ - 1);
                int h = c >> 6;          // c / HD_
                int hd = c & (HD_ - 1);
                C[(((size_t)(b * H_ + h)) * S_ + s) * HD_ + hd] = v;
            } else {
                C[(size_t)r * N + c] = v;
            }
        }
    }
}

// ---------------- fused sparse attention ----------------
#define QT  8     // queries per block (one warp per query)
#define CHK 64    // key/value chunk
#define KVP 68    // padded stride (conflict-free float4 LDS)

#define SMEM_FLOATS (QT * S_ + CHK * KVP + QT * HD_ + QT + QT)
#define SMEM_BYTES  (SMEM_FLOATS * 4 + 256 * 4 + 16)

__global__ __launch_bounds__(256) void attn_kernel(
    const float* __restrict__ Q, const float* __restrict__ K,
    const float* __restrict__ V, float* __restrict__ O)
{
    extern __shared__ float sm[];
    float* sc    = sm;                      // QT*S_ scores -> probabilities
    float* kv    = sc + QT * S_;            // CHK*KVP chunk
    float* qs    = kv + CHK * KVP;          // QT*HD_
    float* s_thr = qs + QT * HD_;           // QT
    float* s_rcp = s_thr + QT;              // QT
    int*   hist  = (int*)(s_rcp + QT);      // 256 bins
    unsigned* s_pref = (unsigned*)(hist + 256);
    int*      s_rank = (int*)(s_pref + 1);

    int tid  = threadIdx.x;
    int lane = tid & 31;
    int w    = tid >> 5;                    // warp id == query index in tile
    int b    = blockIdx.z, h = blockIdx.y;
    int q0   = blockIdx.x * QT;
    size_t headBase = ((size_t)(b * H_ + h)) * S_ * HD_;

    // ---- load Q tile (pre-scaled by 1/sqrt(HD)) ----
    const float* Qp = Q + headBase + (size_t)q0 * HD_;
    for (int i = tid; i < QT * HD_; i += 256) qs[i] = Qp[i] * 0.125f;
    __syncthreads();

    float qreg[HD_];
#pragma unroll
    for (int d = 0; d < HD_; d++) qreg[d] = qs[w * HD_ + d];

    // ---- phase B: scores (warp w computes row w; 2 keys/lane/chunk) ----
    const float* Kp = K + headBase;
    for (int c = 0; c < S_; c += CHK) {
#pragma unroll
        for (int i = tid; i < CHK * HD_ / 4; i += 256) {
            int r = i >> 4;
            int d4 = (i & 15) * 4;
            float4 t = *(const float4*)(Kp + (size_t)(c + r) * HD_ + d4);
            float* dst = kv + r * KVP + d4;
            dst[0] = t.x; dst[1] = t.y; dst[2] = t.z; dst[3] = t.w;
        }
        __syncthreads();
#pragma unroll
        for (int half = 0; half < 2; half++) {
            int r = lane + half * 32;
            const float* kp = kv + r * KVP;
            float s = 0.f;
#pragma unroll
            for (int d = 0; d < HD_; d += 4) {
                float4 k4 = *(const float4*)(kp + d);
                s += qreg[d] * k4.x + qreg[d + 1] * k4.y +
                     qreg[d + 2] * k4.z + qreg[d + 3] * k4.w;
            }
            sc[w * S_ + c + r] = s;
        }
        __syncthreads();
    }

    // ---- phase C: exact k-th-largest threshold per row (MSB radix select) ----
    for (int row = 0; row < QT; row++) {
        if (tid == 0) { *s_pref = 0u; *s_rank = RANK0; }
        for (int pass = 0; pass < 4; pass++) {
            int shift = 24 - pass * 8;
            hist[tid] = 0;
            __syncthreads();
            unsigned pref = *s_pref;
            for (int i = tid; i < S_; i += 256) {
                unsigned bits = __float_as_uint(sc[row * S_ + i]);
                unsigned u = (bits & 0x80000000u) ? ~bits : (bits | 0x80000000u);
                bool ok = (pass == 0) ||
                          ((u >> (shift + 8)) == (pref >> (shift + 8)));
                if (ok) atomicAdd(&hist[(u >> shift) & 255], 1);
            }
            __syncthreads();
            if (tid < 32) {
                int c8[8]; int cnt = 0;
#pragma unroll
                for (int j = 0; j < 8; j++) { c8[j] = hist[lane * 8 + j]; cnt += c8[j]; }
                int inc = cnt;
#pragma unroll
                for (int off = 1; off < 32; off <<= 1) {
                    int n = __shfl_up_sync(0xffffffffu, inc, off);
                    if (lane >= off) inc += n;
                }
                int excl = inc - cnt;
                int r = *s_rank;
                if (r >= excl && r < inc) {
                    int rr = r - excl;
                    int sel = -1;
#pragma unroll
                    for (int j = 0; j < 8; j++) {
                        if (sel < 0) { if (rr < c8[j]) sel = j; else rr -= c8[j]; }
                    }
                    *s_pref = pref | ((unsigned)(lane * 8 + sel) << shift);
                    *s_rank = rr;
                }
            }
            __syncthreads();
        }
        if (tid == 0) {
            unsigned u = *s_pref;
            unsigned bits = (u & 0x80000000u) ? (u ^ 0x80000000u) : ~u;
            s_thr[row] = __uint_as_float(bits);
        }
    }
    __syncthreads();

    // ---- phase D: masked softmax weights (warp per row), unnormalized ----
    {
        float thr = s_thr[w];
        float* rowp = sc + w * S_;
        float m = -1e30f;
        for (int i = lane; i < S_; i += 32) m = fmaxf(m, rowp[i]);
#pragma unroll
        for (int off = 16; off; off >>= 1)
            m = fmaxf(m, __shfl_xor_sync(0xffffffffu, m, off));
        float l = 0.f;
        for (int i = lane; i < S_; i += 32) {
            float s = rowp[i];
            float p = (s >= thr) ? __expf(s - m) : 0.f;
            rowp[i] = p;
            l += p;
        }
#pragma unroll
        for (int off = 16; off; off >>= 1)
            l += __shfl_xor_sync(0xffffffffu, l, off);
        if (lane == 0) s_rcp[w] = 1.0f / l;
    }
    __syncthreads();

    // ---- phase E: out = P @ V (warp per row; half-warp splits keys) ----
    const float* Vp = V + headBase;
    int sub = lane >> 4;             // key half
    int dq  = (lane & 15) * 4;       // 4 dims per lane
    float4 acc = make_float4(0.f, 0.f, 0.f, 0.f);
    for (int c = 0; c < S_; c += CHK) {
#pragma unroll
        for (int i = tid; i < CHK * HD_ / 4; i += 256) {
            int r = i >> 4;
            int d4 = (i & 15) * 4;
            float4 t = *(const float4*)(Vp + (size_t)(c + r) * HD_ + d4);
            float* dst = kv + r * KVP + d4;
            dst[0] = t.x; dst[1] = t.y; dst[2] = t.z; dst[3] = t.w;
        }
        __syncthreads();
        const float* prow = sc + w * S_ + c + sub * 32;
        const float* kvb  = kv + sub * 32 * KVP + dq;
#pragma unroll
        for (int r4 = 0; r4 < 32; r4 += 4) {
            float4 p4 = *(const float4*)(prow + r4);
            {
                float4 vv = *(const float4*)(kvb + (r4 + 0) * KVP);
                acc.x += p4.x * vv.x; acc.y += p4.x * vv.y;
                acc.z += p4.x * vv.z; acc.w += p4.x * vv.w;
            }
            {
                float4 vv = *(const float4*)(kvb + (r4 + 1) * KVP);
                acc.x += p4.y * vv.x; acc.y += p4.y * vv.y;
                acc.z += p4.y * vv.z; acc.w += p4.y * vv.w;
            }
            {
                float4 vv = *(const float4*)(kvb + (r4 + 2) * KVP);
                acc.x += p4.z * vv.x; acc.y += p4.z * vv.y;
                acc.z += p4.z * vv.z; acc.w += p4.z * vv.w;
            }
            {
                float4 vv = *(const float4*)(kvb + (r4 + 3) * KVP);
                acc.x += p4.w * vv.x; acc.y += p4.w * vv.y;
                acc.z += p4.w * vv.z; acc.w += p4.w * vv.w;
            }
        }
        __syncthreads();
    }
    acc.x += __shfl_xor_sync(0xffffffffu, acc.x, 16);
    acc.y += __shfl_xor_sync(0xffffffffu, acc.y, 16);
    acc.z += __shfl_xor_sync(0xffffffffu, acc.z, 16);
    acc.w += __shfl_xor_sync(0xffffffffu, acc.w, 16);
    if (sub == 0) {
        float rcp = s_rcp[w];
        float* op = O + ((size_t)b * S_ + q0 + w) * D_ + h * HD_ + dq;
        op[0] = acc.x * rcp; op[1] = acc.y * rcp;
        op[2] = acc.z * rcp; op[3] = acc.w * rcp;
    }
}

// ---------------- launcher ----------------
extern "C" void kernel_launch(void* const* d_in, const int* in_sizes, int n_in,
                              void* d_out, int out_size)
{
    const float* X  = (const float*)d_in[0];
    const float* Wq = (const float*)d_in[1];
    const float* bq = (const float*)d_in[2];
    const float* Wk = (const float*)d_in[3];
    const float* bk = (const float*)d_in[4];
    const float* Wv = (const float*)d_in[5];
    const float* bv = (const float*)d_in[6];
    const float* Wo = (const float*)d_in[7];
    const float* bo = (const float*)d_in[8];

    // one-time host-side setup (deterministic; cached across calls)
    static float *Qd = nullptr, *Kd = nullptr, *Vd = nullptr, *Ad = nullptr;
    static bool init_done = false;
    if (!init_done) {
        cudaGetSymbolAddress((void**)&Qd, g_Q);
        cudaGetSymbolAddress((void**)&Kd, g_K);
        cudaGetSymbolAddress((void**)&Vd, g_V);
        cudaGetSymbolAddress((void**)&Ad, g_A);
        cudaFuncSetAttribute(attn_kernel,
                             cudaFuncAttributeMaxDynamicSharedMemorySize,
                             SMEM_BYTES);
        init_done = true;
    }

    dim3 ggrid(D_ / BN, (B_ * S_) / BM);
    sgemm_bt<<<ggrid, 256>>>(X, Wq, bq, Qd, B_ * S_, D_, D_, 1);
    sgemm_bt<<<ggrid, 256>>>(X, Wk, bk, Kd, B_ * S_, D_, D_, 1);
    sgemm_bt<<<ggrid, 256>>>(X, Wv, bv, Vd, B_ * S_, D_, D_, 1);

    attn_kernel<<<dim3(S_ / QT, H_, B_), 256, SMEM_BYTES>>>(Qd, Kd, Vd, Ad);

    sgemm_bt<<<ggrid, 256>>>(Ad, Wo, bo, (float*)d_out, B_ * S_, D_, D_, 0);
}

// round 3
// speedup vs baseline: 1.4380x; 1.4380x over previous
#include <cuda_runtime.h>
#include <math.h>

#define B_  2
#define S_  2048
#define D_  1024
#define H_  16
#define HD_ 64
#define KSEL 409
#define RANK0 (S_ - KSEL)   /* 1639: 0-indexed ascending rank of k-th largest */

// ---------------- device scratch (no allocations allowed) ----------------
__device__ float g_Q[B_ * S_ * D_];   // [b,h,s,hd]
__device__ float g_K[B_ * S_ * D_];   // [b,h,s,hd]
__device__ float g_V[B_ * S_ * D_];   // [b,h,s,hd]
__device__ float g_A[B_ * S_ * D_];   // [b,s,d] attention output

// ---------------- SGEMM: C = A(MxK) @ W(NxK)^T + bias ----------------
#define BM 128
#define BN 128
#define BKK 8

__global__ __launch_bounds__(256) void sgemm_bt(
    const float* __restrict__ A, const float* __restrict__ W,
    const float* __restrict__ bias, float* __restrict__ C,
    int M, int N, int K, int headLayout)
{
    __shared__ float As[BKK][BM];
    __shared__ float Bs[BKK][BN];

    int tid = threadIdx.x;
    int bm = blockIdx.y * BM;
    int bn = blockIdx.x * BN;

    int arow = tid >> 1;          // 0..127
    int acol = (tid & 1) * 4;     // 0 or 4
    int tx = tid & 15;            // 0..15
    int ty = tid >> 4;            // 0..15

    float acc[8][8];
#pragma unroll
    for (int i = 0; i < 8; i++)
#pragma unroll
        for (int j = 0; j < 8; j++) acc[i][j] = 0.f;

    for (int k0 = 0; k0 < K; k0 += BKK) {
        float4 a4 = *(const float4*)(A + (size_t)(bm + arow) * K + k0 + acol);
        As[acol + 0][arow] = a4.x; As[acol + 1][arow] = a4.y;
        As[acol + 2][arow] = a4.z; As[acol + 3][arow] = a4.w;
        float4 b4 = *(const float4*)(W + (size_t)(bn + arow) * K + k0 + acol);
        Bs[acol + 0][arow] = b4.x; Bs[acol + 1][arow] = b4.y;
        Bs[acol + 2][arow] = b4.z; Bs[acol + 3][arow] = b4.w;
        __syncthreads();

#pragma unroll
        for (int kk = 0; kk < BKK; kk++) {
            float ar[8], br[8];
            *(float4*)&ar[0] = *(const float4*)&As[kk][ty * 4];
            *(float4*)&ar[4] = *(const float4*)&As[kk][64 + ty * 4];
            *(float4*)&br[0] = *(const float4*)&Bs[kk][tx * 4];
            *(float4*)&br[4] = *(const float4*)&Bs[kk][64 + tx * 4];
#pragma unroll
            for (int i = 0; i < 8; i++)
#pragma unroll
                for (int j = 0; j < 8; j++)
                    acc[i][j] += ar[i] * br[j];
        }
        __syncthreads();
    }

#pragma unroll
    for (int i = 0; i < 8; i++) {
        int r = bm + ((i < 4) ? (ty * 4 + i) : (64 + ty * 4 + i - 4));
#pragma unroll
        for (int j = 0; j < 8; j++) {
            int c = bn + ((j < 4) ? (tx * 4 + j) : (64 + tx * 4 + j - 4));
            float v = acc[i][j] + bias[c];
            if (headLayout) {
                int b = r >> 11;         // r / S_
                int s = r & (S_ - 1);
                int h = c >> 6;          // c / HD_
                int hd = c & (HD_ - 1);
                C[(((size_t)(b * H_ + h)) * S_ + s) * HD_ + hd] = v;
            } else {
                C[(size_t)r * N + c] = v;
            }
        }
    }
}

// ---------------- fused sparse attention (register-tiled) ----------------
#define QT    16        // query rows per block
#define CHUNK 128       // keys per chunk
#define NCH   (S_ / CHUNK)   // 16
#define SCP   2052      // padded score row stride (16B aligned, bank-skewed)
#define KVP2  68        // padded K/V/Q row stride

// smem layout (floats):
#define OFF_SC   0
#define OFF_KV   (QT * SCP)                 // 32832
#define OFF_QS   (OFF_KV + CHUNK * KVP2)    // 41536
#define OFF_PB   (OFF_QS + QT * KVP2)       // 42624
#define OFF_RCP  (OFF_PB + QT * KVP2)       // 43712
#define OFF_HIST (OFF_RCP + 16)             // 43728
#define SMEM_FLOATS (OFF_HIST + QT * 256)   // 47824
#define SMEM_BYTES  (SMEM_FLOATS * 4)       // 191296

__global__ __launch_bounds__(512, 1) void attn_kernel(
    const float* __restrict__ Q, const float* __restrict__ K,
    const float* __restrict__ V, float* __restrict__ O)
{
    extern __shared__ float sm[];
    float* sc    = sm + OFF_SC;     // QT x SCP scores -> probs
    float* kv    = sm + OFF_KV;     // CHUNK x KVP2 K/V chunk
    float* qs    = sm + OFF_QS;     // QT x KVP2 scaled Q
    float* pbuf  = sm + OFF_PB;     // QT x KVP2 partial output
    float* s_rcp = sm + OFF_RCP;    // QT
    int*   hist  = (int*)(sm + OFF_HIST);   // QT x 256

    int tid  = threadIdx.x;
    int lane = tid & 31;
    int w    = tid >> 5;            // 0..15
    int b    = blockIdx.z, h = blockIdx.y;
    int q0   = blockIdx.x * QT;
    size_t headBase = ((size_t)(b * H_ + h)) * S_ * HD_;
    const float* Qp = Q + headBase + (size_t)q0 * HD_;
    const float* Kp = K + headBase;
    const float* Vp = V + headBase;

    // ---- phase A: load Q tile scaled by 1/sqrt(HD) ----
    for (int i = tid; i < QT * HD_; i += 512) {
        int r = i >> 6, d = i & 63;
        qs[r * KVP2 + d] = Qp[r * HD_ + d] * 0.125f;
    }

    // ---- phase B: scores. warp w owns 8 keys/chunk; lane: 1 key x 4 q-rows ----
    int qg = lane >> 3;   // 0..3  (rows qg, qg+4, qg+8, qg+12)
    int kl = lane & 7;    // 0..7  (key = ch*128 + w*8 + kl)
    {
        float4 pf[4];
#pragma unroll
        for (int it = 0; it < 4; it++) {
            int i = tid + it * 512;
            pf[it] = *(const float4*)(Kp + (size_t)(i >> 4) * HD_ + (i & 15) * 4);
        }
        for (int ch = 0; ch < NCH; ch++) {
#pragma unroll
            for (int it = 0; it < 4; it++) {
                int i = tid + it * 512;
                *(float4*)(kv + (i >> 4) * KVP2 + (i & 15) * 4) = pf[it];
            }
            __syncthreads();
            if (ch + 1 < NCH) {
#pragma unroll
                for (int it = 0; it < 4; it++) {
                    int i = tid + it * 512;
                    pf[it] = *(const float4*)(Kp +
                        (size_t)((ch + 1) * CHUNK + (i >> 4)) * HD_ + (i & 15) * 4);
                }
            }
            float acc0 = 0.f, acc1 = 0.f, acc2 = 0.f, acc3 = 0.f;
            const float* krow = kv + (w * 8 + kl) * KVP2;
#pragma unroll
            for (int d4 = 0; d4 < HD_; d4 += 4) {
                float4 kk  = *(const float4*)(krow + d4);
                float4 qv0 = *(const float4*)(qs + qg * KVP2 + d4);
                float4 qv1 = *(const float4*)(qs + (qg + 4) * KVP2 + d4);
                float4 qv2 = *(const float4*)(qs + (qg + 8) * KVP2 + d4);
                float4 qv3 = *(const float4*)(qs + (qg + 12) * KVP2 + d4);
                acc0 += qv0.x * kk.x + qv0.y * kk.y + qv0.z * kk.z + qv0.w * kk.w;
                acc1 += qv1.x * kk.x + qv1.y * kk.y + qv1.z * kk.z + qv1.w * kk.w;
                acc2 += qv2.x * kk.x + qv2.y * kk.y + qv2.z * kk.z + qv2.w * kk.w;
                acc3 += qv3.x * kk.x + qv3.y * kk.y + qv3.z * kk.z + qv3.w * kk.w;
            }
            int key = ch * CHUNK + w * 8 + kl;
            sc[ qg       * SCP + key] = acc0;
            sc[(qg + 4)  * SCP + key] = acc1;
            sc[(qg + 8)  * SCP + key] = acc2;
            sc[(qg + 12) * SCP + key] = acc3;
            __syncthreads();
        }
    }

    // ---- phase C: warp-private radix select (row w), then softmax ----
    {
        unsigned pref = 0u; int rank = RANK0;
        const float* rowp = sc + w * SCP;
        int* hw = hist + w * 256;
        for (int pass = 0; pass < 4; pass++) {
            int shift = 24 - pass * 8;
#pragma unroll
            for (int j = lane; j < 256; j += 32) hw[j] = 0;
            __syncwarp();
            for (int i = lane; i < S_; i += 32) {
                unsigned bits = __float_as_uint(rowp[i]);
                unsigned u = (bits & 0x80000000u) ? ~bits : (bits | 0x80000000u);
                bool ok = (pass == 0) ||
                          ((u >> (shift + 8)) == (pref >> (shift + 8)));
                if (ok) atomicAdd(&hw[(u >> shift) & 255], 1);
            }
            __syncwarp();
            int c8[8]; int cnt = 0;
#pragma unroll
            for (int j = 0; j < 8; j++) { c8[j] = hw[lane * 8 + j]; cnt += c8[j]; }
            int inc = cnt;
#pragma unroll
            for (int off = 1; off < 32; off <<= 1) {
                int n = __shfl_up_sync(0xffffffffu, inc, off);
                if (lane >= off) inc += n;
            }
            int excl = inc - cnt;
            bool found = (rank >= excl) && (rank < inc);
            unsigned npref = pref; int nrank = rank;
            if (found) {
                int rr = rank - excl; int sel = -1;
#pragma unroll
                for (int j = 0; j < 8; j++) {
                    if (sel < 0) { if (rr < c8[j]) sel = j; else rr -= c8[j]; }
                }
                npref = pref | ((unsigned)(lane * 8 + sel) << shift);
                nrank = rr;
            }
            unsigned mask = __ballot_sync(0xffffffffu, found);
            int src = __ffs(mask) - 1;
            pref = __shfl_sync(0xffffffffu, npref, src);
            rank = __shfl_sync(0xffffffffu, nrank, src);
            __syncwarp();
        }
        unsigned tb = (pref & 0x80000000u) ? (pref ^ 0x80000000u) : ~pref;
        float thr = __uint_as_float(tb);

        // ---- phase D: masked softmax weights for row w ----
        float* rowm = sc + w * SCP;
        float m = -1e30f;
        for (int i = lane; i < S_; i += 32) m = fmaxf(m, rowm[i]);
#pragma unroll
        for (int off = 16; off; off >>= 1)
            m = fmaxf(m, __shfl_xor_sync(0xffffffffu, m, off));
        float l = 0.f;
        for (int i = lane; i < S_; i += 32) {
            float s = rowm[i];
            float p = (s >= thr) ? __expf(s - m) : 0.f;
            rowm[i] = p;
            l += p;
        }
#pragma unroll
        for (int off = 16; off; off >>= 1)
            l += __shfl_xor_sync(0xffffffffu, l, off);
        if (lane == 0) s_rcp[w] = 1.0f / l;
    }
    __syncthreads();

    // ---- phase E: out = P @ V. warp: 8-d slab; warp-groups split keys ----
    {
        int dr = w & 7, kh = w >> 3;
        int qi = lane >> 1;
        int dcol = dr * 8 + (lane & 1) * 4;
        float4 acc = make_float4(0.f, 0.f, 0.f, 0.f);
        float4 pf[4];
#pragma unroll
        for (int it = 0; it < 4; it++) {
            int i = tid + it * 512;
            pf[it] = *(const float4*)(Vp + (size_t)(i >> 4) * HD_ + (i & 15) * 4);
        }
        for (int ch = 0; ch < NCH; ch++) {
#pragma unroll
            for (int it = 0; it < 4; it++) {
                int i = tid + it * 512;
                *(float4*)(kv + (i >> 4) * KVP2 + (i & 15) * 4) = pf[it];
            }
            __syncthreads();
            if (ch + 1 < NCH) {
#pragma unroll
                for (int it = 0; it < 4; it++) {
                    int i = tid + it * 512;
                    pf[it] = *(const float4*)(Vp +
                        (size_t)((ch + 1) * CHUNK + (i >> 4)) * HD_ + (i & 15) * 4);
                }
            }
            const float* prow  = sc + qi * SCP + ch * CHUNK + kh * 64;
            const float* vbase = kv + kh * 64 * KVP2 + dcol;
#pragma unroll
            for (int k4 = 0; k4 < 64; k4 += 4) {
                float4 p4 = *(const float4*)(prow + k4);
                float4 v0 = *(const float4*)(vbase + (k4 + 0) * KVP2);
                float4 v1 = *(const float4*)(vbase + (k4 + 1) * KVP2);
                float4 v2 = *(const float4*)(vbase + (k4 + 2) * KVP2);
                float4 v3 = *(const float4*)(vbase + (k4 + 3) * KVP2);
                acc.x += p4.x * v0.x; acc.y += p4.x * v0.y;
                acc.z += p4.x * v0.z; acc.w += p4.x * v0.w;
                acc.x += p4.y * v1.x; acc.y += p4.y * v1.y;
                acc.z += p4.y * v1.z; acc.w += p4.y * v1.w;
                acc.x += p4.z * v2.x; acc.y += p4.z * v2.y;
                acc.z += p4.z * v2.z; acc.w += p4.z * v2.w;
                acc.x += p4.w * v3.x; acc.y += p4.w * v3.y;
                acc.z += p4.w * v3.z; acc.w += p4.w * v3.w;
            }
            __syncthreads();
        }
        if (kh == 1) *(float4*)(pbuf + qi * KVP2 + dcol) = acc;
        __syncthreads();
        if (kh == 0) {
            float4 o2 = *(const float4*)(pbuf + qi * KVP2 + dcol);
            float rcp = s_rcp[qi];
            float4 r;
            r.x = (acc.x + o2.x) * rcp; r.y = (acc.y + o2.y) * rcp;
            r.z = (acc.z + o2.z) * rcp; r.w = (acc.w + o2.w) * rcp;
            float* op = O + ((size_t)b * S_ + q0 + qi) * D_ + h * HD_ + dcol;
            *(float4*)op = r;
        }
    }
}

// ---------------- launcher ----------------
extern "C" void kernel_launch(void* const* d_in, const int* in_sizes, int n_in,
                              void* d_out, int out_size)
{
    const float* X  = (const float*)d_in[0];
    const float* Wq = (const float*)d_in[1];
    const float* bq = (const float*)d_in[2];
    const float* Wk = (const float*)d_in[3];
    const float* bk = (const float*)d_in[4];
    const float* Wv = (const float*)d_in[5];
    const float* bv = (const float*)d_in[6];
    const float* Wo = (const float*)d_in[7];
    const float* bo = (const float*)d_in[8];

    static float *Qd = nullptr, *Kd = nullptr, *Vd = nullptr, *Ad = nullptr;
    static bool init_done = false;
    if (!init_done) {
        cudaGetSymbolAddress((void**)&Qd, g_Q);
        cudaGetSymbolAddress((void**)&Kd, g_K);
        cudaGetSymbolAddress((void**)&Vd, g_V);
        cudaGetSymbolAddress((void**)&Ad, g_A);
        cudaFuncSetAttribute(attn_kernel,
                             cudaFuncAttributeMaxDynamicSharedMemorySize,
                             SMEM_BYTES);
        init_done = true;
    }

    dim3 ggrid(D_ / BN, (B_ * S_) / BM);
    sgemm_bt<<<ggrid, 256>>>(X, Wq, bq, Qd, B_ * S_, D_, D_, 1);
    sgemm_bt<<<ggrid, 256>>>(X, Wk, bk, Kd, B_ * S_, D_, D_, 1);
    sgemm_bt<<<ggrid, 256>>>(X, Wv, bv, Vd, B_ * S_, D_, D_, 1);

    attn_kernel<<<dim3(S_ / QT, H_, B_), 512, SMEM_BYTES>>>(Qd, Kd, Vd, Ad);

    sgemm_bt<<<ggrid, 256>>>(Ad, Wo, bo, (float*)d_out, B_ * S_, D_, D_, 0);
}

// round 6
// speedup vs baseline: 1.5074x; 1.0483x over previous
#include <cuda_runtime.h>
#include <cuda_bf16.h>
#include <mma.h>
#include <math.h>

using namespace nvcuda;

#define B_  2
#define S_  2048
#define D_  1024
#define H_  16
#define HD_ 64
#define KSEL 409
#define RANK0 (S_ - KSEL)   /* 1639: 0-indexed ascending rank of k-th largest */

// ---------------- device scratch (no allocations allowed) ----------------
__device__ float g_Q[B_ * S_ * D_];   // [b,h,s,hd]
__device__ float g_K[B_ * S_ * D_];   // [b,h,s,hd]
__device__ float g_V[B_ * S_ * D_];   // [b,h,s,hd]
__device__ float g_A[B_ * S_ * D_];   // [b,s,d] attention output

// ======== split-bf16 tensor-core GEMM: C = A(MxK) @ W(NxK)^T + bias ========
// Explicit, bit-exact splitting (no opaque conversion intrinsics):
//   b0 = bf16_rn(a); r1 = a - b0 (exact); b1 = bf16_rn(r1); r2 = r1 - b1 (exact);
//   b2 = bf16_rn(r2).  a = b0+b1+b2 + O(2^-24 |a|).
// NSPLIT=3 (Q/K): products sa+sb<=2 (6 MMAs)  -> fp32-class scores
// NSPLIT=2 (V/O): products sa+sb<=1 (3 MMAs)  -> ~1.5e-5 linear error
#define GBM 128
#define GBN 128
#define GBK 32
#define GBKP 40            // bf16 smem row stride (80 B, 16B-aligned rows)
#define GSTG 36            // epilogue staging stride (floats)

// operands: NSPLIT*2 * 128*40 bf16  (3-split: 61440 B); epilogue stage: 73728 B
#define GEMM_SMEM_BYTES 73728

template<int NSPLIT>
__global__ __launch_bounds__(256, 1) void bf16_gemm_bt(
    const float* __restrict__ A, const float* __restrict__ W,
    const float* __restrict__ bias, float* __restrict__ C,
    int headLayout)
{
    extern __shared__ char gsm_raw[];
    __nv_bfloat16* sA = (__nv_bfloat16*)gsm_raw;                 // [NSPLIT][GBM*GBKP]
    __nv_bfloat16* sB = sA + NSPLIT * GBM * GBKP;                // [NSPLIT][GBN*GBKP]

    const int K = D_;
    int tid = threadIdx.x;
    int wid = tid >> 5;
    int wm = wid >> 2;         // 0..1
    int wn = wid & 3;          // 0..3
    int bm = blockIdx.y * GBM;
    int bn = blockIdx.x * GBN;

    wmma::fragment<wmma::accumulator, 16, 16, 16, float> fc[4][2];
#pragma unroll
    for (int i = 0; i < 4; i++)
#pragma unroll
        for (int j = 0; j < 2; j++) wmma::fill_fragment(fc[i][j], 0.0f);

    // load map: linear = tid + it*256 -> row = linear/8, col4 = (linear%8)*4
    float4 pa[4], pb[4];
#pragma unroll
    for (int it = 0; it < 4; it++) {
        int linear = tid + it * 256;
        int row = linear >> 3, col4 = (linear & 7) * 4;
        pa[it] = *(const float4*)(A + (size_t)(bm + row) * K + col4);
        pb[it] = *(const float4*)(W + (size_t)(bn + row) * K + col4);
    }

    const int NT = K / GBK;    // 32 k-tiles
    for (int t = 0; t < NT; t++) {
        // ---- explicit split + store (4 bf16 packed per 8B store) ----
#pragma unroll
        for (int it = 0; it < 4; it++) {
            int linear = tid + it * 256;
            int row = linear >> 3, col4 = (linear & 7) * 4;
            float va[4] = { pa[it].x, pa[it].y, pa[it].z, pa[it].w };
            float vb[4] = { pb[it].x, pb[it].y, pb[it].z, pb[it].w };
            unsigned short ua[NSPLIT][4], ub[NSPLIT][4];
#pragma unroll
            for (int e = 0; e < 4; e++) {
                float ra = va[e], rb = vb[e];
#pragma unroll
                for (int s = 0; s < NSPLIT; s++) {
                    __nv_bfloat16 ba = __float2bfloat16(ra);
                    __nv_bfloat16 bb = __float2bfloat16(rb);
                    ua[s][e] = __bfloat16_as_ushort(ba);
                    ub[s][e] = __bfloat16_as_ushort(bb);
                    ra -= __bfloat162float(ba);
                    rb -= __bfloat162float(bb);
                }
            }
#pragma unroll
            for (int s = 0; s < NSPLIT; s++) {
                uint2 wa, wb;
                wa.x = (unsigned)ua[s][0] | ((unsigned)ua[s][1] << 16);
                wa.y = (unsigned)ua[s][2] | ((unsigned)ua[s][3] << 16);
                wb.x = (unsigned)ub[s][0] | ((unsigned)ub[s][1] << 16);
                wb.y = (unsigned)ub[s][2] | ((unsigned)ub[s][3] << 16);
                *(uint2*)(sA + s * GBM * GBKP + row * GBKP + col4) = wa;
                *(uint2*)(sB + s * GBN * GBKP + row * GBKP + col4) = wb;
            }
        }
        __syncthreads();

        // prefetch next tile (overlaps MMA phase)
        if (t + 1 < NT) {
            int k0 = (t + 1) * GBK;
#pragma unroll
            for (int it = 0; it < 4; it++) {
                int linear = tid + it * 256;
                int row = linear >> 3, col4 = (linear & 7) * 4;
                pa[it] = *(const float4*)(A + (size_t)(bm + row) * K + k0 + col4);
                pb[it] = *(const float4*)(W + (size_t)(bn + row) * K + k0 + col4);
            }
        }

#pragma unroll
        for (int ks = 0; ks < GBK / 16; ks++) {
#pragma unroll
            for (int sa = 0; sa < NSPLIT; sa++) {
                wmma::fragment<wmma::matrix_a, 16, 16, 16, __nv_bfloat16, wmma::row_major> fa[4];
#pragma unroll
                for (int i = 0; i < 4; i++)
                    wmma::load_matrix_sync(fa[i],
                        sA + sa * GBM * GBKP + (wm * 64 + i * 16) * GBKP + ks * 16, GBKP);
#pragma unroll
                for (int sb = 0; sb < NSPLIT - sa; sb++) {
                    wmma::fragment<wmma::matrix_b, 16, 16, 16, __nv_bfloat16, wmma::col_major> fb[2];
#pragma unroll
                    for (int j = 0; j < 2; j++)
                        wmma::load_matrix_sync(fb[j],
                            sB + sb * GBN * GBKP + (wn * 32 + j * 16) * GBKP + ks * 16, GBKP);
#pragma unroll
                    for (int i = 0; i < 4; i++)
#pragma unroll
                        for (int j = 0; j < 2; j++)
                            wmma::mma_sync(fc[i][j], fa[i], fb[j], fc[i][j]);
                }
            }
        }
        __syncthreads();
    }

    // ---- epilogue: stage per-warp tile in smem, write coalesced ----
    float* stage = (float*)gsm_raw + wid * 64 * GSTG;
#pragma unroll
    for (int i = 0; i < 4; i++)
#pragma unroll
        for (int j = 0; j < 2; j++)
            wmma::store_matrix_sync(stage + (i * 16) * GSTG + j * 16, fc[i][j],
                                    GSTG, wmma::mem_row_major);
    __syncwarp();

    int lane = tid & 31;
    for (int idx = lane; idx < 64 * 32; idx += 32) {
        int r = idx >> 5, c = idx & 31;
        int gr = bm + wm * 64 + r;
        int gc = bn + wn * 32 + c;
        float v = stage[r * GSTG + c] + bias[gc];
        if (headLayout) {
            int b = gr >> 11;
            int s = gr & (S_ - 1);
            int h = gc >> 6;
            int hd = gc & (HD_ - 1);
            C[(((size_t)(b * H_ + h)) * S_ + s) * HD_ + hd] = v;
        } else {
            C[(size_t)gr * D_ + gc] = v;
        }
    }
}

// ---------------- fused sparse attention (register-tiled) ----------------
#define QT    16        // query rows per block
#define CHUNK 128       // keys per chunk
#define NCH   (S_ / CHUNK)   // 16
#define SCP   2052      // padded score row stride (16B aligned, bank-skewed)
#define KVP2  68        // padded K/V/Q row stride

// smem layout (floats):
#define OFF_SC   0
#define OFF_KV   (QT * SCP)                 // 32832
#define OFF_QS   (OFF_KV + CHUNK * KVP2)    // 41536
#define OFF_PB   (OFF_QS + QT * KVP2)       // 42624
#define OFF_RCP  (OFF_PB + QT * KVP2)       // 43712
#define OFF_HIST (OFF_RCP + 16)             // 43728
#define SMEM_FLOATS (OFF_HIST + QT * 256)   // 47824
#define SMEM_BYTES  (SMEM_FLOATS * 4)       // 191296

__global__ __launch_bounds__(512, 1) void attn_kernel(
    const float* __restrict__ Q, const float* __restrict__ K,
    const float* __restrict__ V, float* __restrict__ O)
{
    extern __shared__ float sm[];
    float* sc    = sm + OFF_SC;     // QT x SCP scores -> probs
    float* kv    = sm + OFF_KV;     // CHUNK x KVP2 K/V chunk
    float* qs    = sm + OFF_QS;     // QT x KVP2 scaled Q
    float* pbuf  = sm + OFF_PB;     // QT x KVP2 partial output
    float* s_rcp = sm + OFF_RCP;    // QT
    int*   hist  = (int*)(sm + OFF_HIST);   // QT x 256

    int tid  = threadIdx.x;
    int lane = tid & 31;
    int w    = tid >> 5;            // 0..15
    int b    = blockIdx.z, h = blockIdx.y;
    int q0   = blockIdx.x * QT;
    size_t headBase = ((size_t)(b * H_ + h)) * S_ * HD_;
    const float* Qp = Q + headBase + (size_t)q0 * HD_;
    const float* Kp = K + headBase;
    const float* Vp = V + headBase;

    // ---- phase A: load Q tile scaled by 1/sqrt(HD) ----
    for (int i = tid; i < QT * HD_; i += 512) {
        int r = i >> 6, d = i & 63;
        qs[r * KVP2 + d] = Qp[r * HD_ + d] * 0.125f;
    }

    // ---- phase B: scores. warp w owns 8 keys/chunk; lane: 1 key x 4 q-rows ----
    int qg = lane >> 3;   // 0..3  (rows qg, qg+4, qg+8, qg+12)
    int kl = lane & 7;    // 0..7  (key = ch*128 + w*8 + kl)
    {
        float4 pf[4];
#pragma unroll
        for (int it = 0; it < 4; it++) {
            int i = tid + it * 512;
            pf[it] = *(const float4*)(Kp + (size_t)(i >> 4) * HD_ + (i & 15) * 4);
        }
        for (int ch = 0; ch < NCH; ch++) {
#pragma unroll
            for (int it = 0; it < 4; it++) {
                int i = tid + it * 512;
                *(float4*)(kv + (i >> 4) * KVP2 + (i & 15) * 4) = pf[it];
            }
            __syncthreads();
            if (ch + 1 < NCH) {
#pragma unroll
                for (int it = 0; it < 4; it++) {
                    int i = tid + it * 512;
                    pf[it] = *(const float4*)(Kp +
                        (size_t)((ch + 1) * CHUNK + (i >> 4)) * HD_ + (i & 15) * 4);
                }
            }
            float acc0 = 0.f, acc1 = 0.f, acc2 = 0.f, acc3 = 0.f;
            const float* krow = kv + (w * 8 + kl) * KVP2;
#pragma unroll
            for (int d4 = 0; d4 < HD_; d4 += 4) {
                float4 kk  = *(const float4*)(krow + d4);
                float4 qv0 = *(const float4*)(qs + qg * KVP2 + d4);
                float4 qv1 = *(const float4*)(qs + (qg + 4) * KVP2 + d4);
                float4 qv2 = *(const float4*)(qs + (qg + 8) * KVP2 + d4);
                float4 qv3 = *(const float4*)(qs + (qg + 12) * KVP2 + d4);
                acc0 += qv0.x * kk.x + qv0.y * kk.y + qv0.z * kk.z + qv0.w * kk.w;
                acc1 += qv1.x * kk.x + qv1.y * kk.y + qv1.z * kk.z + qv1.w * kk.w;
                acc2 += qv2.x * kk.x + qv2.y * kk.y + qv2.z * kk.z + qv2.w * kk.w;
                acc3 += qv3.x * kk.x + qv3.y * kk.y + qv3.z * kk.z + qv3.w * kk.w;
            }
            int key = ch * CHUNK + w * 8 + kl;
            sc[ qg       * SCP + key] = acc0;
            sc[(qg + 4)  * SCP + key] = acc1;
            sc[(qg + 8)  * SCP + key] = acc2;
            sc[(qg + 12) * SCP + key] = acc3;
            __syncthreads();
        }
    }

    // ---- phase C: warp-private radix select (row w), then softmax ----
    {
        unsigned pref = 0u; int rank = RANK0;
        const float* rowp = sc + w * SCP;
        int* hw = hist + w * 256;
        for (int pass = 0; pass < 4; pass++) {
            int shift = 24 - pass * 8;
#pragma unroll
            for (int j = lane; j < 256; j += 32) hw[j] = 0;
            __syncwarp();
            for (int i = lane; i < S_; i += 32) {
                unsigned bits = __float_as_uint(rowp[i]);
                unsigned u = (bits & 0x80000000u) ? ~bits : (bits | 0x80000000u);
                bool ok = (pass == 0) ||
                          ((u >> (shift + 8)) == (pref >> (shift + 8)));
                if (ok) atomicAdd(&hw[(u >> shift) & 255], 1);
            }
            __syncwarp();
            int c8[8]; int cnt = 0;
#pragma unroll
            for (int j = 0; j < 8; j++) { c8[j] = hw[lane * 8 + j]; cnt += c8[j]; }
            int inc = cnt;
#pragma unroll
            for (int off = 1; off < 32; off <<= 1) {
                int n = __shfl_up_sync(0xffffffffu, inc, off);
                if (lane >= off) inc += n;
            }
            int excl = inc - cnt;
            bool found = (rank >= excl) && (rank < inc);
            unsigned npref = pref; int nrank = rank;
            if (found) {
                int rr = rank - excl; int sel = -1;
#pragma unroll
                for (int j = 0; j < 8; j++) {
                    if (sel < 0) { if (rr < c8[j]) sel = j; else rr -= c8[j]; }
                }
                npref = pref | ((unsigned)(lane * 8 + sel) << shift);
                nrank = rr;
            }
            unsigned mask = __ballot_sync(0xffffffffu, found);
            int src = __ffs(mask) - 1;
            pref = __shfl_sync(0xffffffffu, npref, src);
            rank = __shfl_sync(0xffffffffu, nrank, src);
            __syncwarp();
        }
        unsigned tb = (pref & 0x80000000u) ? (pref ^ 0x80000000u) : ~pref;
        float thr = __uint_as_float(tb);

        // ---- phase D: masked softmax weights for row w ----
        float* rowm = sc + w * SCP;
        float m = -1e30f;
        for (int i = lane; i < S_; i += 32) m = fmaxf(m, rowm[i]);
#pragma unroll
        for (int off = 16; off; off >>= 1)
            m = fmaxf(m, __shfl_xor_sync(0xffffffffu, m, off));
        float l = 0.f;
        for (int i = lane; i < S_; i += 32) {
            float s = rowm[i];
            float p = (s >= thr) ? __expf(s - m) : 0.f;
            rowm[i] = p;
            l += p;
        }
#pragma unroll
        for (int off = 16; off; off >>= 1)
            l += __shfl_xor_sync(0xffffffffu, l, off);
        if (lane == 0) s_rcp[w] = 1.0f / l;
    }
    __syncthreads();

    // ---- phase E: out = P @ V. warp: 8-d slab; warp-groups split keys ----
    {
        int dr = w & 7, kh = w >> 3;
        int qi = lane >> 1;
        int dcol = dr * 8 + (lane & 1) * 4;
        float4 acc = make_float4(0.f, 0.f, 0.f, 0.f);
        float4 pf[4];
#pragma unroll
        for (int it = 0; it < 4; it++) {
            int i = tid + it * 512;
            pf[it] = *(const float4*)(Vp + (size_t)(i >> 4) * HD_ + (i & 15) * 4);
        }
        for (int ch = 0; ch < NCH; ch++) {
#pragma unroll
            for (int it = 0; it < 4; it++) {
                int i = tid + it * 512;
                *(float4*)(kv + (i >> 4) * KVP2 + (i & 15) * 4) = pf[it];
            }
            __syncthreads();
            if (ch + 1 < NCH) {
#pragma unroll
                for (int it = 0; it < 4; it++) {
                    int i = tid + it * 512;
                    pf[it] = *(const float4*)(Vp +
                        (size_t)((ch + 1) * CHUNK + (i >> 4)) * HD_ + (i & 15) * 4);
                }
            }
            const float* prow  = sc + qi * SCP + ch * CHUNK + kh * 64;
            const float* vbase = kv + kh * 64 * KVP2 + dcol;
#pragma unroll
            for (int k4 = 0; k4 < 64; k4 += 4) {
                float4 p4 = *(const float4*)(prow + k4);
                float4 v0 = *(const float4*)(vbase + (k4 + 0) * KVP2);
                float4 v1 = *(const float4*)(vbase + (k4 + 1) * KVP2);
                float4 v2 = *(const float4*)(vbase + (k4 + 2) * KVP2);
                float4 v3 = *(const float4*)(vbase + (k4 + 3) * KVP2);
                acc.x += p4.x * v0.x; acc.y += p4.x * v0.y;
                acc.z += p4.x * v0.z; acc.w += p4.x * v0.w;
                acc.x += p4.y * v1.x; acc.y += p4.y * v1.y;
                acc.z += p4.y * v1.z; acc.w += p4.y * v1.w;
                acc.x += p4.z * v2.x; acc.y += p4.z * v2.y;
                acc.z += p4.z * v2.z; acc.w += p4.z * v2.w;
                acc.x += p4.w * v3.x; acc.y += p4.w * v3.y;
                acc.z += p4.w * v3.z; acc.w += p4.w * v3.w;
            }
            __syncthreads();
        }
        if (kh == 1) *(float4*)(pbuf + qi * KVP2 + dcol) = acc;
        __syncthreads();
        if (kh == 0) {
            float4 o2 = *(const float4*)(pbuf + qi * KVP2 + dcol);
            float rcp = s_rcp[qi];
            float4 r;
            r.x = (acc.x + o2.x) * rcp; r.y = (acc.y + o2.y) * rcp;
            r.z = (acc.z + o2.z) * rcp; r.w = (acc.w + o2.w) * rcp;
            float* op = O + ((size_t)b * S_ + q0 + qi) * D_ + h * HD_ + dcol;
            *(float4*)op = r;
        }
    }
}

// ---------------- launcher ----------------
extern "C" void kernel_launch(void* const* d_in, const int* in_sizes, int n_in,
                              void* d_out, int out_size)
{
    const float* X  = (const float*)d_in[0];
    const float* Wq = (const float*)d_in[1];
    const float* bq = (const float*)d_in[2];
    const float* Wk = (const float*)d_in[3];
    const float* bk = (const float*)d_in[4];
    const float* Wv = (const float*)d_in[5];
    const float* bv = (const float*)d_in[6];
    const float* Wo = (const float*)d_in[7];
    const float* bo = (const float*)d_in[8];

    static float *Qd = nullptr, *Kd = nullptr, *Vd = nullptr, *Ad = nullptr;
    static bool init_done = false;
    if (!init_done) {
        cudaGetSymbolAddress((void**)&Qd, g_Q);
        cudaGetSymbolAddress((void**)&Kd, g_K);
        cudaGetSymbolAddress((void**)&Vd, g_V);
        cudaGetSymbolAddress((void**)&Ad, g_A);
        cudaFuncSetAttribute(attn_kernel,
                             cudaFuncAttributeMaxDynamicSharedMemorySize,
                             SMEM_BYTES);
        cudaFuncSetAttribute(bf16_gemm_bt<3>,
                             cudaFuncAttributeMaxDynamicSharedMemorySize,
                             GEMM_SMEM_BYTES);
        cudaFuncSetAttribute(bf16_gemm_bt<2>,
                             cudaFuncAttributeMaxDynamicSharedMemorySize,
                             GEMM_SMEM_BYTES);
        init_done = true;
    }

    dim3 ggrid(D_ / GBN, (B_ * S_) / GBM);
    // Q, K: high-precision path (threshold-sensitive)
    bf16_gemm_bt<3><<<ggrid, 256, GEMM_SMEM_BYTES>>>(X, Wq, bq, Qd, 1);
    bf16_gemm_bt<3><<<ggrid, 256, GEMM_SMEM_BYTES>>>(X, Wk, bk, Kd, 1);
    // V: linear-error path
    bf16_gemm_bt<2><<<ggrid, 256, GEMM_SMEM_BYTES>>>(X, Wv, bv, Vd, 1);

    attn_kernel<<<dim3(S_ / QT, H_, B_), 512, SMEM_BYTES>>>(Qd, Kd, Vd, Ad);

    // O: linear-error path
    bf16_gemm_bt<2><<<ggrid, 256, GEMM_SMEM_BYTES>>>(Ad, Wo, bo, (float*)d_out, 0);
}